// round 10
// baseline (speedup 1.0000x reference)
#include <cuda_runtime.h>
#include <cuda_fp8.h>
#include <cuda_bf16.h>
#include <cstdint>

#define KDIM 2048
#define BLK  128
#define NKB  (KDIM / BLK)   // 16 K-blocks
#define M_MAX 8192
#define N_MAX 2048

// Scratch (allocation-free rule: __device__ globals)
__device__ __align__(16) uint8_t g_xq[(size_t)M_MAX * KDIM];    // 16 MB fp8 x
__device__ float g_xs[M_MAX * NKB];                              // per (m,kb) scales
__device__ __align__(16) uint8_t g_wq[(size_t)N_MAX * KDIM];    // 4 MB canonical fp8 w
__device__ int g_wfmt;                                           // 0=raw8, 1=f32, 2=bf16

// ---------------------------------------------------------------------------
// Kernel 0a: detect how the harness materialized the fp8 weight tensor.
// ---------------------------------------------------------------------------
__device__ __forceinline__ bool plaus_e4m3(float v) {
    if (!isfinite(v)) return false;
    float a = fabsf(v);
    if (a == 0.0f) return true;
    if (a < 0.001953125f || a > 448.0f) return false;
    __nv_fp8_storage_t q = __nv_cvt_float_to_fp8(v, __NV_SATFINITE, __NV_E4M3);
    float back = __half2float(__nv_cvt_fp8_to_halfraw(q, __NV_E4M3));
    return back == v;
}

__global__ void detect_wfmt_kernel(const void* __restrict__ w) {
    int lane = threadIdx.x;
    bool ok32 = true, okbf = true;
    for (int i = lane; i < 256; i += 32) {
        float v32 = reinterpret_cast<const float*>(w)[i];
        ok32 = ok32 && plaus_e4m3(v32);
        float vbf = __bfloat162float(reinterpret_cast<const __nv_bfloat16*>(w)[i]);
        okbf = okbf && plaus_e4m3(vbf);
    }
    ok32 = __all_sync(0xffffffffu, ok32);
    okbf = __all_sync(0xffffffffu, okbf);
    if (lane == 0) g_wfmt = ok32 ? 1 : (okbf ? 2 : 0);
}

// ---------------------------------------------------------------------------
// Kernel 0b: canonicalize weight into raw e4m3 bytes in g_wq.
// ---------------------------------------------------------------------------
__global__ void convert_w_kernel(const void* __restrict__ w, int nelem) {
    int i = (blockIdx.x * blockDim.x + threadIdx.x) * 16;
    if (i >= nelem) return;
    const int fmt = g_wfmt;
    uint8_t o[16];
    if (fmt == 1) {
        const float4* p = reinterpret_cast<const float4*>(
            reinterpret_cast<const float*>(w) + i);
#pragma unroll
        for (int j = 0; j < 4; j++) {
            float4 v = p[j];
            o[4 * j + 0] = (uint8_t)__nv_cvt_float_to_fp8(v.x, __NV_SATFINITE, __NV_E4M3);
            o[4 * j + 1] = (uint8_t)__nv_cvt_float_to_fp8(v.y, __NV_SATFINITE, __NV_E4M3);
            o[4 * j + 2] = (uint8_t)__nv_cvt_float_to_fp8(v.z, __NV_SATFINITE, __NV_E4M3);
            o[4 * j + 3] = (uint8_t)__nv_cvt_float_to_fp8(v.w, __NV_SATFINITE, __NV_E4M3);
        }
        *reinterpret_cast<uint4*>(g_wq + i) = *reinterpret_cast<uint4*>(o);
    } else if (fmt == 2) {
        const __nv_bfloat16* p = reinterpret_cast<const __nv_bfloat16*>(w) + i;
#pragma unroll
        for (int j = 0; j < 16; j++)
            o[j] = (uint8_t)__nv_cvt_float_to_fp8(__bfloat162float(p[j]),
                                                  __NV_SATFINITE, __NV_E4M3);
        *reinterpret_cast<uint4*>(g_wq + i) = *reinterpret_cast<uint4*>(o);
    } else {
        *reinterpret_cast<uint4*>(g_wq + i) =
            reinterpret_cast<const uint4*>(reinterpret_cast<const uint8_t*>(w) + i)[0];
    }
}

// ---------------------------------------------------------------------------
// Kernel 1: blockwise activation quantization (one warp per (m, kb) block).
// ---------------------------------------------------------------------------
__global__ void quant_x_kernel(const float* __restrict__ x, int M) {
    int gw   = (blockIdx.x * blockDim.x + threadIdx.x) >> 5;
    int lane = threadIdx.x & 31;
    int m    = gw >> 4;       // / NKB
    int kb   = gw & 15;
    if (m >= M) return;

    float4 v = reinterpret_cast<const float4*>(x + (size_t)m * KDIM + kb * BLK)[lane];
    float a = fmaxf(fmaxf(fabsf(v.x), fabsf(v.y)), fmaxf(fabsf(v.z), fabsf(v.w)));
#pragma unroll
    for (int o = 16; o > 0; o >>= 1) a = fmaxf(a, __shfl_xor_sync(0xffffffffu, a, o));

    a = fmaxf(a, 1e-12f);
    float s = __fdiv_rn(a, 448.0f);     // stored scale: bit-matches reference
    float r = __fdiv_rn(448.0f, a);     // fast per-element quant multiplier
    uint32_t q;
    q  = (uint32_t)__nv_cvt_float_to_fp8(v.x * r, __NV_SATFINITE, __NV_E4M3);
    q |= (uint32_t)__nv_cvt_float_to_fp8(v.y * r, __NV_SATFINITE, __NV_E4M3) << 8;
    q |= (uint32_t)__nv_cvt_float_to_fp8(v.z * r, __NV_SATFINITE, __NV_E4M3) << 16;
    q |= (uint32_t)__nv_cvt_float_to_fp8(v.w * r, __NV_SATFINITE, __NV_E4M3) << 24;

    reinterpret_cast<uint32_t*>(g_xq + (size_t)m * KDIM + kb * BLK)[lane] = q;
    if (lane == 0) g_xs[m * NKB + kb] = s;
}

// ---------------------------------------------------------------------------
// Kernel 2: fp8 mma.sync GEMM. 512 threads, warp grid 4x4, warp tile 16x32,
// CTA tile 64x128, 3-stage cp.async pipeline. __launch_bounds__(512,2) caps
// regs at 64 -> 2 CTAs (1024 threads, 32 warps) resident per SM: doubles the
// warps available to cover LDSM/MMA latency vs the 128-reg variants.
// ---------------------------------------------------------------------------
__device__ __forceinline__ uint32_t su32(const void* p) {
    uint32_t a;
    asm("{ .reg .u64 t; cvta.to.shared.u64 t, %1; cvt.u32.u64 %0, t; }" : "=r"(a) : "l"(p));
    return a;
}

#define LDMX4(r0, r1, r2, r3, addr)                                            \
    asm volatile("ldmatrix.sync.aligned.m8n8.x4.shared.b16 {%0,%1,%2,%3}, [%4];" \
                 : "=r"(r0), "=r"(r1), "=r"(r2), "=r"(r3) : "r"(addr))

#define MMA_E4M3(d, a, b)                                                      \
    asm volatile("mma.sync.aligned.m16n8k32.row.col.f32.e4m3.e4m3.f32 "        \
                 "{%0,%1,%2,%3}, {%4,%5,%6,%7}, {%8,%9}, {%0,%1,%2,%3};"       \
                 : "+f"((d)[0]), "+f"((d)[1]), "+f"((d)[2]), "+f"((d)[3])      \
                 : "r"((a)[0]), "r"((a)[1]), "r"((a)[2]), "r"((a)[3]),         \
                   "r"((b)[0]), "r"((b)[1]))

#define CP16(saddr, gptr)                                                      \
    asm volatile("cp.async.cg.shared.global [%0], [%1], 16;" :: "r"(saddr), "l"(gptr))

// dynamic smem layout: 3 stages x (8K A + 16K B), then scales
#define STG_BYTES 24576
#define B_OFF     8192
#define XS_OFF   (3 * STG_BYTES)             // 73728
#define WS_OFF   (XS_OFF + 64 * NKB * 4)     // + 4KB x-scales (64 rows)
#define SMEM_TOT (WS_OFF + NKB * 4)

__global__ void __launch_bounds__(512, 2)
gemm_fp8_mma(const float* __restrict__ wsc, float* __restrict__ out, int M, int N) {
    extern __shared__ uint8_t smem[];
    float* xs_s = reinterpret_cast<float*>(smem + XS_OFF);
    float* ws_s = reinterpret_cast<float*>(smem + WS_OFF);

    const int tid  = threadIdx.x;
    const int lane = tid & 31;
    const int wid  = tid >> 5;
    const int wm   = wid >> 2;      // 0..3  (16-row warp tile, 64-row CTA tile)
    const int wn   = wid & 3;       // 0..3  (32-col warp tile, 128-col CTA tile)
    const int m0 = blockIdx.x * 64;
    const int n0 = blockIdx.y * 128;

    {
        const float* xsg = g_xs + (size_t)m0 * NKB;
        for (int i = tid; i < 64 * NKB; i += 512) xs_s[i] = xsg[i];
        if (tid < NKB) ws_s[tid] = wsc[(n0 >> 7) * NKB + tid];
    }

    const uint32_t sa0 = su32(smem);

    // fragment source rows (mf=0 slice of the validated R4/R6 mapping)
    const int a_row = wm * 16 + (lane & 7) + ((lane >> 3) & 1) * 8;
    const int a_k16 = ((lane >> 4) & 1) * 16;
    const int b_row = wn * 32 + (lane & 7) + ((lane >> 4) & 1) * 8;
    const int b_k16 = ((lane >> 3) & 1) * 16;

    // stage loaders (512 threads):
    //   A tile 64x128B:  8 thr/row, 1 x 16B per thread
    //   B tile 128x128B: 4 thr/row, 2 x 16B per thread (cols c, c+64)
    const int la_row = tid >> 3, la_c = (tid & 7) * 16;
    const int lb_row = tid >> 2, lb_c = (tid & 3) * 16;
    const uint8_t* agp = g_xq + (size_t)(m0 + la_row) * KDIM + la_c;
    const uint8_t* bgp = g_wq + (size_t)(n0 + lb_row) * KDIM + lb_c;
    int a_st, b_st[2];
    {
        int off = la_row * 128 + la_c;
        a_st = off ^ ((off >> 3) & 0x70);
    }
#pragma unroll
    for (int i = 0; i < 2; i++) {
        int off = lb_row * 128 + lb_c + i * 64;
        b_st[i] = off ^ ((off >> 3) & 0x70);
    }

    float pacc[4][4];
#pragma unroll
    for (int j = 0; j < 4; j++)
#pragma unroll
        for (int c = 0; c < 4; c++) pacc[j][c] = 0.0f;

#define LOAD_STAGE(kb, s)                                                      \
    do {                                                                       \
        uint32_t da = sa0 + (s) * STG_BYTES;                                   \
        uint32_t db = da + B_OFF;                                              \
        CP16(da + a_st, agp + (kb) * BLK);                                     \
        _Pragma("unroll")                                                      \
        for (int i = 0; i < 2; i++)                                            \
            CP16(db + b_st[i], bgp + (kb) * BLK + i * 64);                     \
        asm volatile("cp.async.commit_group;");                                \
    } while (0)

// one k-block of compute + scale fixup, on stage s of the smem ring
#define COMPUTE_KB(kb, s)                                                      \
    do {                                                                       \
        const uint32_t ta = sa0 + (s) * STG_BYTES;                             \
        const uint32_t tb = ta + B_OFF;                                        \
        float lacc[4][4];                                                      \
        _Pragma("unroll")                                                      \
        for (int j = 0; j < 4; j++)                                            \
            _Pragma("unroll")                                                  \
            for (int c = 0; c < 4; c++) lacc[j][c] = 0.0f;                     \
        _Pragma("unroll")                                                      \
        for (int kc = 0; kc < 4; kc++) {                                       \
            uint32_t af[4];                                                    \
            {                                                                  \
                int off = a_row * 128 + kc * 32 + a_k16;                       \
                int sw  = off ^ ((off >> 3) & 0x70);                           \
                LDMX4(af[0], af[1], af[2], af[3], ta + sw);                    \
            }                                                                  \
            uint32_t bf[4][2];                                                 \
            _Pragma("unroll")                                                  \
            for (int nj = 0; nj < 2; nj++) {                                   \
                int off = (b_row + nj * 16) * 128 + kc * 32 + b_k16;           \
                int sw  = off ^ ((off >> 3) & 0x70);                           \
                uint32_t r0, r1, r2, r3;                                       \
                LDMX4(r0, r1, r2, r3, tb + sw);                                \
                bf[nj * 2][0] = r0; bf[nj * 2][1] = r1;                        \
                bf[nj * 2 + 1][0] = r2; bf[nj * 2 + 1][1] = r3;                \
            }                                                                  \
            _Pragma("unroll")                                                  \
            for (int nf = 0; nf < 4; nf++)                                     \
                MMA_E4M3(lacc[nf], af, bf[nf]);                                \
        }                                                                      \
        const float wskb = ws_s[kb];                                           \
        {                                                                      \
            int r0 = wm * 16 + (lane >> 2);                                    \
            float s0 = xs_s[r0 * NKB + (kb)] * wskb;                           \
            float s1 = xs_s[(r0 + 8) * NKB + (kb)] * wskb;                     \
            _Pragma("unroll")                                                  \
            for (int nf = 0; nf < 4; nf++) {                                   \
                pacc[nf][0] = fmaf(lacc[nf][0], s0, pacc[nf][0]);              \
                pacc[nf][1] = fmaf(lacc[nf][1], s0, pacc[nf][1]);              \
                pacc[nf][2] = fmaf(lacc[nf][2], s1, pacc[nf][2]);              \
                pacc[nf][3] = fmaf(lacc[nf][3], s1, pacc[nf][3]);              \
            }                                                                  \
        }                                                                      \
    } while (0)

    LOAD_STAGE(0, 0);
    LOAD_STAGE(1, 1);

    // main loop (validated R6 structure): per-kb wait+barrier, 3-stage ring
    for (int kb = 0; kb < NKB - 1; kb++) {
        const int s = kb % 3;
        asm volatile("cp.async.wait_group 1;");
        __syncthreads();
        // stage (kb+2)%3 was last read in iteration kb-1 (completed before
        // this barrier), so it is free to refill now.
        if (kb + 2 < NKB) LOAD_STAGE(kb + 2, (kb + 2) % 3);
        COMPUTE_KB(kb, s);
    }
    {
        const int kb = NKB - 1, s = (NKB - 1) % 3;
        asm volatile("cp.async.wait_group 0;");
        __syncthreads();
        COMPUTE_KB(kb, s);
    }

    // epilogue: fragment-direct float2 stores
    {
        int r0 = m0 + wm * 16 + (lane >> 2);
#pragma unroll
        for (int nf = 0; nf < 4; nf++) {
            int c = n0 + wn * 32 + nf * 8 + (lane & 3) * 2;
            *reinterpret_cast<float2*>(out + (size_t)r0 * N + c) =
                make_float2(pacc[nf][0], pacc[nf][1]);
            *reinterpret_cast<float2*>(out + (size_t)(r0 + 8) * N + c) =
                make_float2(pacc[nf][2], pacc[nf][3]);
        }
    }
}

// ---------------------------------------------------------------------------
extern "C" void kernel_launch(void* const* d_in, const int* in_sizes, int n_in,
                              void* d_out, int out_size) {
    const float* x  = (const float*)d_in[0];
    const void*  w  = d_in[1];                     // fp8 weight, representation detected
    const float* ws = (const float*)d_in[2];       // [N/128, K/128] fp32
    float* out = (float*)d_out;

    const int M = in_sizes[0] / KDIM;              // 8192
    const int N = in_sizes[1] / KDIM;              // 2048
    const int WN = in_sizes[1];                    // N*K elements

    detect_wfmt_kernel<<<1, 32>>>(w);
    convert_w_kernel<<<(WN / 16 + 255) / 256, 256>>>(w, WN);
    quant_x_kernel<<<(M * NKB) / 4, 128>>>(x, M);

    static int smem_set = 0;
    if (!smem_set) {
        cudaFuncSetAttribute(gemm_fp8_mma,
                             cudaFuncAttributeMaxDynamicSharedMemorySize, SMEM_TOT);
        smem_set = 1;
    }
    dim3 grid(M / 64, N / 128);
    gemm_fp8_mma<<<grid, 512, SMEM_TOT>>>(ws, out, M, N);
}

// round 11
// speedup vs baseline: 1.0167x; 1.0167x over previous
#include <cuda_runtime.h>
#include <cuda_fp8.h>
#include <cuda_bf16.h>
#include <cstdint>

#define KDIM 2048
#define BLK  128
#define NKB  (KDIM / BLK)   // 16 K-blocks
#define M_MAX 8192
#define N_MAX 2048

// Scratch (allocation-free rule: __device__ globals)
__device__ __align__(16) uint8_t g_xq[(size_t)M_MAX * KDIM];    // 16 MB fp8 x
__device__ float g_xs[M_MAX * NKB];                              // per (m,kb) scales
__device__ __align__(16) uint8_t g_wq[(size_t)N_MAX * KDIM];    // 4 MB canonical fp8 w
__device__ int g_wfmt;                                           // 0=raw8, 1=f32, 2=bf16

// ---------------------------------------------------------------------------
// Kernel 0a: detect how the harness materialized the fp8 weight tensor.
// ---------------------------------------------------------------------------
__device__ __forceinline__ bool plaus_e4m3(float v) {
    if (!isfinite(v)) return false;
    float a = fabsf(v);
    if (a == 0.0f) return true;
    if (a < 0.001953125f || a > 448.0f) return false;
    __nv_fp8_storage_t q = __nv_cvt_float_to_fp8(v, __NV_SATFINITE, __NV_E4M3);
    float back = __half2float(__nv_cvt_fp8_to_halfraw(q, __NV_E4M3));
    return back == v;
}

__global__ void detect_wfmt_kernel(const void* __restrict__ w) {
    int lane = threadIdx.x;
    bool ok32 = true, okbf = true;
    for (int i = lane; i < 256; i += 32) {
        float v32 = reinterpret_cast<const float*>(w)[i];
        ok32 = ok32 && plaus_e4m3(v32);
        float vbf = __bfloat162float(reinterpret_cast<const __nv_bfloat16*>(w)[i]);
        okbf = okbf && plaus_e4m3(vbf);
    }
    ok32 = __all_sync(0xffffffffu, ok32);
    okbf = __all_sync(0xffffffffu, okbf);
    if (lane == 0) g_wfmt = ok32 ? 1 : (okbf ? 2 : 0);
}

// ---------------------------------------------------------------------------
// Kernel 0b: canonicalize weight into raw e4m3 bytes in g_wq.
// ---------------------------------------------------------------------------
__global__ void convert_w_kernel(const void* __restrict__ w, int nelem) {
    int i = (blockIdx.x * blockDim.x + threadIdx.x) * 16;
    if (i >= nelem) return;
    const int fmt = g_wfmt;
    uint8_t o[16];
    if (fmt == 1) {
        const float4* p = reinterpret_cast<const float4*>(
            reinterpret_cast<const float*>(w) + i);
#pragma unroll
        for (int j = 0; j < 4; j++) {
            float4 v = p[j];
            o[4 * j + 0] = (uint8_t)__nv_cvt_float_to_fp8(v.x, __NV_SATFINITE, __NV_E4M3);
            o[4 * j + 1] = (uint8_t)__nv_cvt_float_to_fp8(v.y, __NV_SATFINITE, __NV_E4M3);
            o[4 * j + 2] = (uint8_t)__nv_cvt_float_to_fp8(v.z, __NV_SATFINITE, __NV_E4M3);
            o[4 * j + 3] = (uint8_t)__nv_cvt_float_to_fp8(v.w, __NV_SATFINITE, __NV_E4M3);
        }
        *reinterpret_cast<uint4*>(g_wq + i) = *reinterpret_cast<uint4*>(o);
    } else if (fmt == 2) {
        const __nv_bfloat16* p = reinterpret_cast<const __nv_bfloat16*>(w) + i;
#pragma unroll
        for (int j = 0; j < 16; j++)
            o[j] = (uint8_t)__nv_cvt_float_to_fp8(__bfloat162float(p[j]),
                                                  __NV_SATFINITE, __NV_E4M3);
        *reinterpret_cast<uint4*>(g_wq + i) = *reinterpret_cast<uint4*>(o);
    } else {
        *reinterpret_cast<uint4*>(g_wq + i) =
            reinterpret_cast<const uint4*>(reinterpret_cast<const uint8_t*>(w) + i)[0];
    }
}

// ---------------------------------------------------------------------------
// Kernel 1: blockwise activation quantization (one warp per (m, kb) block).
// ---------------------------------------------------------------------------
__global__ void quant_x_kernel(const float* __restrict__ x, int M) {
    int gw   = (blockIdx.x * blockDim.x + threadIdx.x) >> 5;
    int lane = threadIdx.x & 31;
    int m    = gw >> 4;       // / NKB
    int kb   = gw & 15;
    if (m >= M) return;

    float4 v = reinterpret_cast<const float4*>(x + (size_t)m * KDIM + kb * BLK)[lane];
    float a = fmaxf(fmaxf(fabsf(v.x), fabsf(v.y)), fmaxf(fabsf(v.z), fabsf(v.w)));
#pragma unroll
    for (int o = 16; o > 0; o >>= 1) a = fmaxf(a, __shfl_xor_sync(0xffffffffu, a, o));

    a = fmaxf(a, 1e-12f);
    float s = __fdiv_rn(a, 448.0f);     // stored scale: bit-matches reference
    float r = __fdiv_rn(448.0f, a);     // fast per-element quant multiplier
    uint32_t q;
    q  = (uint32_t)__nv_cvt_float_to_fp8(v.x * r, __NV_SATFINITE, __NV_E4M3);
    q |= (uint32_t)__nv_cvt_float_to_fp8(v.y * r, __NV_SATFINITE, __NV_E4M3) << 8;
    q |= (uint32_t)__nv_cvt_float_to_fp8(v.z * r, __NV_SATFINITE, __NV_E4M3) << 16;
    q |= (uint32_t)__nv_cvt_float_to_fp8(v.w * r, __NV_SATFINITE, __NV_E4M3) << 24;

    reinterpret_cast<uint32_t*>(g_xq + (size_t)m * KDIM + kb * BLK)[lane] = q;
    if (lane == 0) g_xs[m * NKB + kb] = s;
}

// ---------------------------------------------------------------------------
// Kernel 2: fp8 mma.sync GEMM with telescoping-rescale accumulation.
// 256 threads, warp grid 4x2, warp tile 32x64, CTA tile 128x128.
// ONE accumulator set: MMA accumulates in place (C operand); between k-blocks
// acc *= sc_{kb-1}/sc_kb per row; final acc *= sc_15. Freed registers buy the
// fatter tile (21.3 MACs per smem byte vs 16 for 32x32).
// ---------------------------------------------------------------------------
__device__ __forceinline__ uint32_t su32(const void* p) {
    uint32_t a;
    asm("{ .reg .u64 t; cvta.to.shared.u64 t, %1; cvt.u32.u64 %0, t; }" : "=r"(a) : "l"(p));
    return a;
}

#define LDMX4(r0, r1, r2, r3, addr)                                            \
    asm volatile("ldmatrix.sync.aligned.m8n8.x4.shared.b16 {%0,%1,%2,%3}, [%4];" \
                 : "=r"(r0), "=r"(r1), "=r"(r2), "=r"(r3) : "r"(addr))

#define MMA_E4M3(d, a, b)                                                      \
    asm volatile("mma.sync.aligned.m16n8k32.row.col.f32.e4m3.e4m3.f32 "        \
                 "{%0,%1,%2,%3}, {%4,%5,%6,%7}, {%8,%9}, {%0,%1,%2,%3};"       \
                 : "+f"((d)[0]), "+f"((d)[1]), "+f"((d)[2]), "+f"((d)[3])      \
                 : "r"((a)[0]), "r"((a)[1]), "r"((a)[2]), "r"((a)[3]),         \
                   "r"((b)[0]), "r"((b)[1]))

#define CP16(saddr, gptr)                                                      \
    asm volatile("cp.async.cg.shared.global [%0], [%1], 16;" :: "r"(saddr), "l"(gptr))

// dynamic smem: 3 stages x (16K A + 16K B), ratio table, final-scale table
#define STG_BYTES 32768
#define B_OFF     16384
#define RT_OFF   (3 * STG_BYTES)             // 98304: 128 rows x 16 kb ratios
#define FIN_OFF  (RT_OFF + 128 * NKB * 4)    // +8KB: 128 final scales
#define SMEM_TOT (FIN_OFF + 128 * 4)

__global__ void __launch_bounds__(256, 2)
gemm_fp8_mma(const float* __restrict__ wsc, float* __restrict__ out, int M, int N) {
    extern __shared__ uint8_t smem[];
    float* rt_s  = reinterpret_cast<float*>(smem + RT_OFF);
    float* fin_s = reinterpret_cast<float*>(smem + FIN_OFF);

    const int tid  = threadIdx.x;
    const int lane = tid & 31;
    const int wid  = tid >> 5;
    const int wm   = wid >> 1;      // 0..3  (32-row warp tile)
    const int wn   = wid & 1;       // 0..1  (64-col warp tile)
    const int m0 = blockIdx.x * 128;
    const int n0 = blockIdx.y * 128;

    // build per-row rescale table: rt[m][kb] = sc[m][kb-1]/sc[m][kb],
    // fin[m] = sc[m][NKB-1], where sc = xs[m,kb]*ws[nb,kb]. One-time cost.
    {
        const float* xsg = g_xs + (size_t)m0 * NKB;
        const float* wsg = wsc + (n0 >> 7) * NKB;
        for (int i = tid; i < 128 * NKB; i += 256) {
            int m = i >> 4, kb = i & 15;
            float cur = xsg[m * NKB + kb] * wsg[kb];
            float prev = kb ? xsg[m * NKB + kb - 1] * wsg[kb - 1] : cur;
            rt_s[i] = __fdiv_rn(prev, cur);
            if (kb == NKB - 1) fin_s[m] = cur;
        }
    }

    const uint32_t sa0 = su32(smem);

    // fragment source rows (validated mapping)
    const int a_row = wm * 32 + (lane & 7) + ((lane >> 3) & 1) * 8;
    const int a_k16 = ((lane >> 4) & 1) * 16;
    const int b_row = wn * 64 + (lane & 7) + ((lane >> 4) & 1) * 8;
    const int b_k16 = ((lane >> 3) & 1) * 16;

    // stage loader: A 128x128B and B 128x128B, 2 thr/row, 4 x 16B each
    const int l_row = tid >> 1, l_c = (tid & 1) * 16;
    const uint8_t* agp = g_xq + (size_t)(m0 + l_row) * KDIM + l_c;
    const uint8_t* bgp = g_wq + (size_t)(n0 + l_row) * KDIM + l_c;
    int sw_st[4];
#pragma unroll
    for (int i = 0; i < 4; i++) {
        int off = l_row * 128 + l_c + i * 32;
        sw_st[i] = off ^ ((off >> 3) & 0x70);
    }

    // single accumulator set: 2 mf x 8 nf x 4 = 64 floats
    float acc[2][8][4];
#pragma unroll
    for (int i = 0; i < 2; i++)
#pragma unroll
        for (int j = 0; j < 8; j++)
#pragma unroll
            for (int c = 0; c < 4; c++) acc[i][j][c] = 0.0f;

#define LOAD_STAGE(kb, s)                                                      \
    do {                                                                       \
        uint32_t da = sa0 + (s) * STG_BYTES;                                   \
        uint32_t db = da + B_OFF;                                              \
        _Pragma("unroll")                                                      \
        for (int i = 0; i < 4; i++) {                                          \
            CP16(da + sw_st[i], agp + (kb) * BLK + i * 32);                    \
            CP16(db + sw_st[i], bgp + (kb) * BLK + i * 32);                    \
        }                                                                      \
        asm volatile("cp.async.commit_group;");                                \
    } while (0)

// rescale acc by per-row ratio (kb > 0 only), then MMA-accumulate the k-block
#define COMPUTE_KB(kb, s)                                                      \
    do {                                                                       \
        if (kb) {                                                              \
            _Pragma("unroll")                                                  \
            for (int mf = 0; mf < 2; mf++) {                                   \
                int r0 = wm * 32 + mf * 16 + (lane >> 2);                      \
                float rlo = rt_s[r0 * NKB + (kb)];                             \
                float rhi = rt_s[(r0 + 8) * NKB + (kb)];                       \
                _Pragma("unroll")                                              \
                for (int nf = 0; nf < 8; nf++) {                               \
                    acc[mf][nf][0] *= rlo; acc[mf][nf][1] *= rlo;              \
                    acc[mf][nf][2] *= rhi; acc[mf][nf][3] *= rhi;              \
                }                                                              \
            }                                                                  \
        }                                                                      \
        const uint32_t ta = sa0 + (s) * STG_BYTES;                             \
        const uint32_t tb = ta + B_OFF;                                        \
        _Pragma("unroll")                                                      \
        for (int kc = 0; kc < 4; kc++) {                                       \
            uint32_t af[2][4];                                                 \
            _Pragma("unroll")                                                  \
            for (int mf = 0; mf < 2; mf++) {                                   \
                int off = (a_row + mf * 16) * 128 + kc * 32 + a_k16;           \
                int sw  = off ^ ((off >> 3) & 0x70);                           \
                LDMX4(af[mf][0], af[mf][1], af[mf][2], af[mf][3], ta + sw);    \
            }                                                                  \
            uint32_t bf[8][2];                                                 \
            _Pragma("unroll")                                                  \
            for (int nj = 0; nj < 4; nj++) {                                   \
                int off = (b_row + nj * 16) * 128 + kc * 32 + b_k16;           \
                int sw  = off ^ ((off >> 3) & 0x70);                           \
                uint32_t r0, r1, r2, r3;                                       \
                LDMX4(r0, r1, r2, r3, tb + sw);                                \
                bf[nj * 2][0] = r0; bf[nj * 2][1] = r1;                        \
                bf[nj * 2 + 1][0] = r2; bf[nj * 2 + 1][1] = r3;                \
            }                                                                  \
            _Pragma("unroll")                                                  \
            for (int mf = 0; mf < 2; mf++)                                     \
                _Pragma("unroll")                                              \
                for (int nf = 0; nf < 8; nf++)                                 \
                    MMA_E4M3(acc[mf][nf], af[mf], bf[nf]);                     \
        }                                                                      \
    } while (0)

    LOAD_STAGE(0, 0);
    LOAD_STAGE(1, 1);

    // main loop (validated R6 structure): per-kb wait+barrier, 3-stage ring.
    // The kb=0 barrier also publishes the rescale table built above.
    for (int kb = 0; kb < NKB - 1; kb++) {
        const int s = kb % 3;
        asm volatile("cp.async.wait_group 1;");
        __syncthreads();
        // stage (kb+2)%3 was last read in iteration kb-1 (completed before
        // this barrier), so it is free to refill now.
        if (kb + 2 < NKB) LOAD_STAGE(kb + 2, (kb + 2) % 3);
        COMPUTE_KB(kb, s);
    }
    {
        const int kb = NKB - 1, s = (NKB - 1) % 3;
        asm volatile("cp.async.wait_group 0;");
        __syncthreads();
        COMPUTE_KB(kb, s);
    }

    // epilogue: apply final scale sc[m][NKB-1], fragment-direct float2 stores
#pragma unroll
    for (int mf = 0; mf < 2; mf++) {
        int rl = wm * 32 + mf * 16 + (lane >> 2);
        float flo = fin_s[rl], fhi = fin_s[rl + 8];
        int r0 = m0 + rl;
#pragma unroll
        for (int nf = 0; nf < 8; nf++) {
            int c = n0 + wn * 64 + nf * 8 + (lane & 3) * 2;
            *reinterpret_cast<float2*>(out + (size_t)r0 * N + c) =
                make_float2(acc[mf][nf][0] * flo, acc[mf][nf][1] * flo);
            *reinterpret_cast<float2*>(out + (size_t)(r0 + 8) * N + c) =
                make_float2(acc[mf][nf][2] * fhi, acc[mf][nf][3] * fhi);
        }
    }
}

// ---------------------------------------------------------------------------
extern "C" void kernel_launch(void* const* d_in, const int* in_sizes, int n_in,
                              void* d_out, int out_size) {
    const float* x  = (const float*)d_in[0];
    const void*  w  = d_in[1];                     // fp8 weight, representation detected
    const float* ws = (const float*)d_in[2];       // [N/128, K/128] fp32
    float* out = (float*)d_out;

    const int M = in_sizes[0] / KDIM;              // 8192
    const int N = in_sizes[1] / KDIM;              // 2048
    const int WN = in_sizes[1];                    // N*K elements

    detect_wfmt_kernel<<<1, 32>>>(w);
    convert_w_kernel<<<(WN / 16 + 255) / 256, 256>>>(w, WN);
    quant_x_kernel<<<(M * NKB) / 4, 128>>>(x, M);

    static int smem_set = 0;
    if (!smem_set) {
        cudaFuncSetAttribute(gemm_fp8_mma,
                             cudaFuncAttributeMaxDynamicSharedMemorySize, SMEM_TOT);
        smem_set = 1;
    }
    dim3 grid(M / 128, N / 128);
    gemm_fp8_mma<<<grid, 256, SMEM_TOT>>>(ws, out, M, N);
}

// round 13
// speedup vs baseline: 1.0987x; 1.0807x over previous
#include <cuda_runtime.h>
#include <cuda_fp8.h>
#include <cuda_bf16.h>
#include <cstdint>

#define KDIM 2048
#define BLK  128
#define NKB  (KDIM / BLK)   // 16 K-blocks
#define M_MAX 8192
#define N_MAX 2048

// Scratch (allocation-free rule: __device__ globals)
__device__ __align__(16) uint8_t g_xq[(size_t)M_MAX * KDIM];    // 16 MB fp8 x
__device__ float g_xs[M_MAX * NKB];                              // per (m,kb) scales
__device__ __align__(16) uint8_t g_wq[(size_t)N_MAX * KDIM];    // 4 MB canonical fp8 w
__device__ int g_wfmt;                                           // 0=raw8, 1=f32, 2=bf16

// ---------------------------------------------------------------------------
// Kernel 0a: detect how the harness materialized the fp8 weight tensor.
// ---------------------------------------------------------------------------
__device__ __forceinline__ bool plaus_e4m3(float v) {
    if (!isfinite(v)) return false;
    float a = fabsf(v);
    if (a == 0.0f) return true;
    if (a < 0.001953125f || a > 448.0f) return false;
    __nv_fp8_storage_t q = __nv_cvt_float_to_fp8(v, __NV_SATFINITE, __NV_E4M3);
    float back = __half2float(__nv_cvt_fp8_to_halfraw(q, __NV_E4M3));
    return back == v;
}

__global__ void detect_wfmt_kernel(const void* __restrict__ w) {
    int lane = threadIdx.x;
    bool ok32 = true, okbf = true;
    for (int i = lane; i < 256; i += 32) {
        float v32 = reinterpret_cast<const float*>(w)[i];
        ok32 = ok32 && plaus_e4m3(v32);
        float vbf = __bfloat162float(reinterpret_cast<const __nv_bfloat16*>(w)[i]);
        okbf = okbf && plaus_e4m3(vbf);
    }
    ok32 = __all_sync(0xffffffffu, ok32);
    okbf = __all_sync(0xffffffffu, okbf);
    if (lane == 0) g_wfmt = ok32 ? 1 : (okbf ? 2 : 0);
}

// ---------------------------------------------------------------------------
// Kernel 0b: canonicalize weight into raw e4m3 bytes in g_wq.
// ---------------------------------------------------------------------------
__global__ void convert_w_kernel(const void* __restrict__ w, int nelem) {
    int i = (blockIdx.x * blockDim.x + threadIdx.x) * 16;
    if (i >= nelem) return;
    const int fmt = g_wfmt;
    uint8_t o[16];
    if (fmt == 1) {
        const float4* p = reinterpret_cast<const float4*>(
            reinterpret_cast<const float*>(w) + i);
#pragma unroll
        for (int j = 0; j < 4; j++) {
            float4 v = p[j];
            o[4 * j + 0] = (uint8_t)__nv_cvt_float_to_fp8(v.x, __NV_SATFINITE, __NV_E4M3);
            o[4 * j + 1] = (uint8_t)__nv_cvt_float_to_fp8(v.y, __NV_SATFINITE, __NV_E4M3);
            o[4 * j + 2] = (uint8_t)__nv_cvt_float_to_fp8(v.z, __NV_SATFINITE, __NV_E4M3);
            o[4 * j + 3] = (uint8_t)__nv_cvt_float_to_fp8(v.w, __NV_SATFINITE, __NV_E4M3);
        }
        *reinterpret_cast<uint4*>(g_wq + i) = *reinterpret_cast<uint4*>(o);
    } else if (fmt == 2) {
        const __nv_bfloat16* p = reinterpret_cast<const __nv_bfloat16*>(w) + i;
#pragma unroll
        for (int j = 0; j < 16; j++)
            o[j] = (uint8_t)__nv_cvt_float_to_fp8(__bfloat162float(p[j]),
                                                  __NV_SATFINITE, __NV_E4M3);
        *reinterpret_cast<uint4*>(g_wq + i) = *reinterpret_cast<uint4*>(o);
    } else {
        *reinterpret_cast<uint4*>(g_wq + i) =
            reinterpret_cast<const uint4*>(reinterpret_cast<const uint8_t*>(w) + i)[0];
    }
}

// ---------------------------------------------------------------------------
// Kernel 1: blockwise activation quantization (one warp per (m, kb) block).
// Scale s computed with exact fdiv (matches reference); element quant uses a
// broadcast reciprocal multiply (measured good in R8/R10/R11: rel_err 7.55e-5).
// ---------------------------------------------------------------------------
__global__ void quant_x_kernel(const float* __restrict__ x, int M) {
    int gw   = (blockIdx.x * blockDim.x + threadIdx.x) >> 5;
    int lane = threadIdx.x & 31;
    int m    = gw >> 4;       // / NKB
    int kb   = gw & 15;
    if (m >= M) return;

    float4 v = reinterpret_cast<const float4*>(x + (size_t)m * KDIM + kb * BLK)[lane];
    float a = fmaxf(fmaxf(fabsf(v.x), fabsf(v.y)), fmaxf(fabsf(v.z), fabsf(v.w)));
#pragma unroll
    for (int o = 16; o > 0; o >>= 1) a = fmaxf(a, __shfl_xor_sync(0xffffffffu, a, o));

    a = fmaxf(a, 1e-12f);
    float s = __fdiv_rn(a, 448.0f);     // stored scale: bit-matches reference
    float r = __fdiv_rn(448.0f, a);     // fast per-element quant multiplier
    uint32_t q;
    q  = (uint32_t)__nv_cvt_float_to_fp8(v.x * r, __NV_SATFINITE, __NV_E4M3);
    q |= (uint32_t)__nv_cvt_float_to_fp8(v.y * r, __NV_SATFINITE, __NV_E4M3) << 8;
    q |= (uint32_t)__nv_cvt_float_to_fp8(v.z * r, __NV_SATFINITE, __NV_E4M3) << 16;
    q |= (uint32_t)__nv_cvt_float_to_fp8(v.w * r, __NV_SATFINITE, __NV_E4M3) << 24;

    reinterpret_cast<uint32_t*>(g_xq + (size_t)m * KDIM + kb * BLK)[lane] = q;
    if (lane == 0) g_xs[m * NKB + kb] = s;
}

// ---------------------------------------------------------------------------
// Kernel 2: fp8 mma.sync GEMM — byte-exact R6 body (best measured: 221.9us).
// 512 threads, warp grid 4x4, 32x32 warp tiles, CTA 128x128, 3-stage
// cp.async ring, per-kb wait+barrier, inline swizzles, runtime k-loop.
// ---------------------------------------------------------------------------
__device__ __forceinline__ uint32_t su32(const void* p) {
    uint32_t a;
    asm("{ .reg .u64 t; cvta.to.shared.u64 t, %1; cvt.u32.u64 %0, t; }" : "=r"(a) : "l"(p));
    return a;
}

#define LDMX4(r0, r1, r2, r3, addr)                                            \
    asm volatile("ldmatrix.sync.aligned.m8n8.x4.shared.b16 {%0,%1,%2,%3}, [%4];" \
                 : "=r"(r0), "=r"(r1), "=r"(r2), "=r"(r3) : "r"(addr))

#define MMA_E4M3(d, a, b)                                                      \
    asm volatile("mma.sync.aligned.m16n8k32.row.col.f32.e4m3.e4m3.f32 "        \
                 "{%0,%1,%2,%3}, {%4,%5,%6,%7}, {%8,%9}, {%0,%1,%2,%3};"       \
                 : "+f"((d)[0]), "+f"((d)[1]), "+f"((d)[2]), "+f"((d)[3])      \
                 : "r"((a)[0]), "r"((a)[1]), "r"((a)[2]), "r"((a)[3]),         \
                   "r"((b)[0]), "r"((b)[1]))

#define CP16(saddr, gptr)                                                      \
    asm volatile("cp.async.cg.shared.global [%0], [%1], 16;" :: "r"(saddr), "l"(gptr))

// dynamic smem layout: 3 stages x (16K A + 16K B), then scales
#define STG_BYTES 32768
#define XS_OFF   (3 * STG_BYTES)
#define WS_OFF   (XS_OFF + 128 * NKB * 4)
#define SMEM_TOT (WS_OFF + NKB * 4)

__global__ void __launch_bounds__(512, 1)
gemm_fp8_mma(const float* __restrict__ wsc, float* __restrict__ out, int M, int N) {
    extern __shared__ uint8_t smem[];
    float* xs_s = reinterpret_cast<float*>(smem + XS_OFF);
    float* ws_s = reinterpret_cast<float*>(smem + WS_OFF);

    const int tid  = threadIdx.x;
    const int lane = tid & 31;
    const int wid  = tid >> 5;
    const int wm   = wid >> 2;      // 0..3  (32-row warp tile)
    const int wn   = wid & 3;       // 0..3  (32-col warp tile)
    const int m0 = blockIdx.x * 128;
    const int n0 = blockIdx.y * 128;

    {
        const float* xsg = g_xs + (size_t)m0 * NKB;
        for (int i = tid; i < 128 * NKB; i += 512) xs_s[i] = xsg[i];
        if (tid < NKB) ws_s[tid] = wsc[(n0 >> 7) * NKB + tid];
    }

    const uint32_t sa0 = su32(smem);

    // fragment source rows (validated mapping)
    const int a_row = wm * 32 + (lane & 7) + ((lane >> 3) & 1) * 8;
    const int a_k16 = ((lane >> 4) & 1) * 16;
    const int b_row = wn * 32 + (lane & 7) + ((lane >> 4) & 1) * 8;
    const int b_k16 = ((lane >> 3) & 1) * 16;

    // stage loader: 4 threads per row, 2 x 16B per matrix per thread;
    // global pointers precomputed once, stepped by kb*BLK
    const int l_row = tid >> 2;                    // 0..127
    const int l_c16 = (tid & 3) * 16;
    const uint8_t* agp = g_xq + (size_t)m0 * KDIM + (size_t)l_row * KDIM + l_c16;
    const uint8_t* bgp = g_wq + (size_t)n0 * KDIM + (size_t)l_row * KDIM + l_c16;
    int sw_st[2];
#pragma unroll
    for (int i = 0; i < 2; i++) {
        int off = l_row * 128 + l_c16 + i * 64;
        sw_st[i] = off ^ ((off >> 3) & 0x70);
    }

    float pacc[2][4][4];
#pragma unroll
    for (int i = 0; i < 2; i++)
#pragma unroll
        for (int j = 0; j < 4; j++)
#pragma unroll
            for (int c = 0; c < 4; c++) pacc[i][j][c] = 0.0f;

#define LOAD_STAGE(kb, s)                                                      \
    do {                                                                       \
        uint32_t da = sa0 + (s) * STG_BYTES;                                   \
        uint32_t db = da + 16384;                                              \
        _Pragma("unroll")                                                      \
        for (int i = 0; i < 2; i++) {                                          \
            CP16(da + sw_st[i], agp + (kb) * BLK + i * 64);                    \
            CP16(db + sw_st[i], bgp + (kb) * BLK + i * 64);                    \
        }                                                                      \
        asm volatile("cp.async.commit_group;");                                \
    } while (0)

// one k-block of compute + scale fixup, on stage s of the smem ring
#define COMPUTE_KB(kb, s)                                                      \
    do {                                                                       \
        const uint32_t ta = sa0 + (s) * STG_BYTES;                             \
        const uint32_t tb = ta + 16384;                                        \
        float lacc[2][4][4];                                                   \
        _Pragma("unroll")                                                      \
        for (int i = 0; i < 2; i++)                                            \
            _Pragma("unroll")                                                  \
            for (int j = 0; j < 4; j++)                                        \
                _Pragma("unroll")                                              \
                for (int c = 0; c < 4; c++) lacc[i][j][c] = 0.0f;              \
        _Pragma("unroll")                                                      \
        for (int kc = 0; kc < 4; kc++) {                                       \
            uint32_t af[2][4];                                                 \
            _Pragma("unroll")                                                  \
            for (int mf = 0; mf < 2; mf++) {                                   \
                int off = (a_row + mf * 16) * 128 + kc * 32 + a_k16;           \
                int sw  = off ^ ((off >> 3) & 0x70);                           \
                LDMX4(af[mf][0], af[mf][1], af[mf][2], af[mf][3], ta + sw);    \
            }                                                                  \
            uint32_t bf[4][2];                                                 \
            _Pragma("unroll")                                                  \
            for (int nj = 0; nj < 2; nj++) {                                   \
                int off = (b_row + nj * 16) * 128 + kc * 32 + b_k16;           \
                int sw  = off ^ ((off >> 3) & 0x70);                           \
                uint32_t r0, r1, r2, r3;                                       \
                LDMX4(r0, r1, r2, r3, tb + sw);                                \
                bf[nj * 2][0] = r0; bf[nj * 2][1] = r1;                        \
                bf[nj * 2 + 1][0] = r2; bf[nj * 2 + 1][1] = r3;                \
            }                                                                  \
            _Pragma("unroll")                                                  \
            for (int mf = 0; mf < 2; mf++)                                     \
                _Pragma("unroll")                                              \
                for (int nf = 0; nf < 4; nf++)                                 \
                    MMA_E4M3(lacc[mf][nf], af[mf], bf[nf]);                    \
        }                                                                      \
        const float wskb = ws_s[kb];                                           \
        _Pragma("unroll")                                                      \
        for (int mf = 0; mf < 2; mf++) {                                       \
            int r0 = wm * 32 + mf * 16 + (lane >> 2);                          \
            float s0 = xs_s[r0 * NKB + (kb)] * wskb;                           \
            float s1 = xs_s[(r0 + 8) * NKB + (kb)] * wskb;                     \
            _Pragma("unroll")                                                  \
            for (int nf = 0; nf < 4; nf++) {                                   \
                pacc[mf][nf][0] = fmaf(lacc[mf][nf][0], s0, pacc[mf][nf][0]);  \
                pacc[mf][nf][1] = fmaf(lacc[mf][nf][1], s0, pacc[mf][nf][1]);  \
                pacc[mf][nf][2] = fmaf(lacc[mf][nf][2], s1, pacc[mf][nf][2]);  \
                pacc[mf][nf][3] = fmaf(lacc[mf][nf][3], s1, pacc[mf][nf][3]);  \
            }                                                                  \
        }                                                                      \
    } while (0)

    LOAD_STAGE(0, 0);
    LOAD_STAGE(1, 1);

    // main loop (validated R6 structure): per-kb wait+barrier, 3-stage ring,
    // last iteration peeled for the final wait depth
    for (int kb = 0; kb < NKB - 1; kb++) {
        const int s = kb % 3;
        asm volatile("cp.async.wait_group 1;");
        __syncthreads();
        // stage (kb+2)%3 was last read in iteration kb-1 (completed before
        // this barrier), so it is free to refill now.
        if (kb + 2 < NKB) LOAD_STAGE(kb + 2, (kb + 2) % 3);
        COMPUTE_KB(kb, s);
    }
    {
        const int kb = NKB - 1, s = (NKB - 1) % 3;
        asm volatile("cp.async.wait_group 0;");
        __syncthreads();
        COMPUTE_KB(kb, s);
    }

    // epilogue: fragment-direct float2 stores
#pragma unroll
    for (int mf = 0; mf < 2; mf++) {
        int r0 = m0 + wm * 32 + mf * 16 + (lane >> 2);
#pragma unroll
        for (int nf = 0; nf < 4; nf++) {
            int c = n0 + wn * 32 + nf * 8 + (lane & 3) * 2;
            *reinterpret_cast<float2*>(out + (size_t)r0 * N + c) =
                make_float2(pacc[mf][nf][0], pacc[mf][nf][1]);
            *reinterpret_cast<float2*>(out + (size_t)(r0 + 8) * N + c) =
                make_float2(pacc[mf][nf][2], pacc[mf][nf][3]);
        }
    }
}

// ---------------------------------------------------------------------------
extern "C" void kernel_launch(void* const* d_in, const int* in_sizes, int n_in,
                              void* d_out, int out_size) {
    const float* x  = (const float*)d_in[0];
    const void*  w  = d_in[1];                     // fp8 weight, representation detected
    const float* ws = (const float*)d_in[2];       // [N/128, K/128] fp32
    float* out = (float*)d_out;

    const int M = in_sizes[0] / KDIM;              // 8192
    const int N = in_sizes[1] / KDIM;              // 2048
    const int WN = in_sizes[1];                    // N*K elements

    detect_wfmt_kernel<<<1, 32>>>(w);
    convert_w_kernel<<<(WN / 16 + 255) / 256, 256>>>(w, WN);
    quant_x_kernel<<<(M * NKB) / 4, 128>>>(x, M);

    static int smem_set = 0;
    if (!smem_set) {
        cudaFuncSetAttribute(gemm_fp8_mma,
                             cudaFuncAttributeMaxDynamicSharedMemorySize, SMEM_TOT);
        smem_set = 1;
    }
    dim3 grid(M / 128, N / 128);
    gemm_fp8_mma<<<grid, 512, SMEM_TOT>>>(ws, out, M, N);
}

// round 14
// speedup vs baseline: 1.1325x; 1.0308x over previous
#include <cuda_runtime.h>
#include <cuda_fp8.h>
#include <cuda_bf16.h>
#include <cstdint>

#define KDIM 2048
#define BLK  128
#define NKB  (KDIM / BLK)   // 16 K-blocks
#define M_MAX 8192
#define N_MAX 2048

// Scratch (allocation-free rule: __device__ globals)
__device__ __align__(16) uint8_t g_xq[(size_t)M_MAX * KDIM];    // 16 MB fp8 x
__device__ float g_xs[M_MAX * NKB];                              // per (m,kb) scales
__device__ __align__(16) uint8_t g_wq[(size_t)N_MAX * KDIM];    // 4 MB canonical fp8 w

// ---------------------------------------------------------------------------
// packed fp32x2 -> e4m3x2 convert (RN, satfinite — identical rounding to
// __nv_cvt_float_to_fp8). dst.lo = second operand, dst.hi = first operand.
// ---------------------------------------------------------------------------
#define CVT2_E4M3(dst16, vhi, vlo)                                             \
    asm("cvt.rn.satfinite.e4m3x2.f32 %0, %1, %2;"                              \
        : "=h"(dst16) : "f"(vhi), "f"(vlo))

__device__ __forceinline__ bool plaus_e4m3(float v) {
    if (!isfinite(v)) return false;
    float a = fabsf(v);
    if (a == 0.0f) return true;
    if (a < 0.001953125f || a > 448.0f) return false;
    __nv_fp8_storage_t q = __nv_cvt_float_to_fp8(v, __NV_SATFINITE, __NV_E4M3);
    float back = __half2float(__nv_cvt_fp8_to_halfraw(q, __NV_E4M3));
    return back == v;
}

// ---------------------------------------------------------------------------
// Fused prep kernel (256 threads/block):
//   blocks [0, cb):        weight canonicalization -> g_wq (per-block format
//                          detection on the first 256 elements, all L2 hits)
//   blocks [cb, cb+qb):    blockwise x quantization (one warp per (m,kb))
// ---------------------------------------------------------------------------
__global__ void __launch_bounds__(256)
prep_kernel(const float* __restrict__ x, const void* __restrict__ w,
            int M, int wnelem) {
    const int cb  = wnelem / 4096;            // convert blocks (4096 elems each)
    const int tid = threadIdx.x;

    if ((int)blockIdx.x < cb) {
        // ---- per-block format detection (redundant, cheap) ----
        bool ok32, okbf;
        {
            float v32 = reinterpret_cast<const float*>(w)[tid];
            ok32 = plaus_e4m3(v32);
            float vbf = __bfloat162float(
                reinterpret_cast<const __nv_bfloat16*>(w)[tid]);
            okbf = plaus_e4m3(vbf);
        }
        ok32 = __syncthreads_and(ok32);
        okbf = __syncthreads_and(okbf);
        const int fmt = ok32 ? 1 : (okbf ? 2 : 0);

        // ---- convert 16 elements per thread ----
        const int i = blockIdx.x * 4096 + tid * 16;
        uint32_t o[4];
        if (fmt == 1) {
            const float4* p = reinterpret_cast<const float4*>(
                reinterpret_cast<const float*>(w) + i);
#pragma unroll
            for (int j = 0; j < 4; j++) {
                float4 v = p[j];
                uint16_t lo, hi;
                CVT2_E4M3(lo, v.y, v.x);
                CVT2_E4M3(hi, v.w, v.z);
                o[j] = (uint32_t)lo | ((uint32_t)hi << 16);
            }
        } else if (fmt == 2) {
            const __nv_bfloat16* p = reinterpret_cast<const __nv_bfloat16*>(w) + i;
#pragma unroll
            for (int j = 0; j < 4; j++) {
                float v0 = __bfloat162float(p[4 * j + 0]);
                float v1 = __bfloat162float(p[4 * j + 1]);
                float v2 = __bfloat162float(p[4 * j + 2]);
                float v3 = __bfloat162float(p[4 * j + 3]);
                uint16_t lo, hi;
                CVT2_E4M3(lo, v1, v0);
                CVT2_E4M3(hi, v3, v2);
                o[j] = (uint32_t)lo | ((uint32_t)hi << 16);
            }
        } else {
            *reinterpret_cast<uint4*>(&o[0]) =
                reinterpret_cast<const uint4*>(
                    reinterpret_cast<const uint8_t*>(w) + i)[0];
        }
        *reinterpret_cast<uint4*>(g_wq + i) = *reinterpret_cast<uint4*>(o);
    } else {
        // ---- activation quantization: one warp per (m, kb) block ----
        int gw   = ((blockIdx.x - cb) * 256 + tid) >> 5;
        int lane = tid & 31;
        int m    = gw >> 4;       // / NKB
        int kb   = gw & 15;
        if (m >= M) return;

        float4 v = reinterpret_cast<const float4*>(
            x + (size_t)m * KDIM + kb * BLK)[lane];
        float a = fmaxf(fmaxf(fabsf(v.x), fabsf(v.y)),
                        fmaxf(fabsf(v.z), fabsf(v.w)));
#pragma unroll
        for (int o2 = 16; o2 > 0; o2 >>= 1)
            a = fmaxf(a, __shfl_xor_sync(0xffffffffu, a, o2));

        a = fmaxf(a, 1e-12f);
        float s = __fdiv_rn(a, 448.0f);     // stored scale: bit-matches reference
        float r = __fdiv_rn(448.0f, a);     // fast per-element quant multiplier
        uint16_t p01, p23;
        CVT2_E4M3(p01, v.y * r, v.x * r);
        CVT2_E4M3(p23, v.w * r, v.z * r);
        uint32_t q = (uint32_t)p01 | ((uint32_t)p23 << 16);

        reinterpret_cast<uint32_t*>(g_xq + (size_t)m * KDIM + kb * BLK)[lane] = q;
        if (lane == 0) g_xs[m * NKB + kb] = s;
    }
}

// ---------------------------------------------------------------------------
// Kernel 2: fp8 mma.sync GEMM — byte-exact R6/R13 body (222us, reproduced
// twice; tensor pipe saturated at the legacy-QMMA ceiling).
// 512 threads, warp grid 4x4, 32x32 warp tiles, CTA 128x128, 3-stage
// cp.async ring, per-kb wait+barrier, inline swizzles, runtime k-loop.
// ---------------------------------------------------------------------------
__device__ __forceinline__ uint32_t su32(const void* p) {
    uint32_t a;
    asm("{ .reg .u64 t; cvta.to.shared.u64 t, %1; cvt.u32.u64 %0, t; }" : "=r"(a) : "l"(p));
    return a;
}

#define LDMX4(r0, r1, r2, r3, addr)                                            \
    asm volatile("ldmatrix.sync.aligned.m8n8.x4.shared.b16 {%0,%1,%2,%3}, [%4];" \
                 : "=r"(r0), "=r"(r1), "=r"(r2), "=r"(r3) : "r"(addr))

#define MMA_E4M3(d, a, b)                                                      \
    asm volatile("mma.sync.aligned.m16n8k32.row.col.f32.e4m3.e4m3.f32 "        \
                 "{%0,%1,%2,%3}, {%4,%5,%6,%7}, {%8,%9}, {%0,%1,%2,%3};"       \
                 : "+f"((d)[0]), "+f"((d)[1]), "+f"((d)[2]), "+f"((d)[3])      \
                 : "r"((a)[0]), "r"((a)[1]), "r"((a)[2]), "r"((a)[3]),         \
                   "r"((b)[0]), "r"((b)[1]))

#define CP16(saddr, gptr)                                                      \
    asm volatile("cp.async.cg.shared.global [%0], [%1], 16;" :: "r"(saddr), "l"(gptr))

// dynamic smem layout: 3 stages x (16K A + 16K B), then scales
#define STG_BYTES 32768
#define XS_OFF   (3 * STG_BYTES)
#define WS_OFF   (XS_OFF + 128 * NKB * 4)
#define SMEM_TOT (WS_OFF + NKB * 4)

__global__ void __launch_bounds__(512, 1)
gemm_fp8_mma(const float* __restrict__ wsc, float* __restrict__ out, int M, int N) {
    extern __shared__ uint8_t smem[];
    float* xs_s = reinterpret_cast<float*>(smem + XS_OFF);
    float* ws_s = reinterpret_cast<float*>(smem + WS_OFF);

    const int tid  = threadIdx.x;
    const int lane = tid & 31;
    const int wid  = tid >> 5;
    const int wm   = wid >> 2;      // 0..3  (32-row warp tile)
    const int wn   = wid & 3;       // 0..3  (32-col warp tile)
    const int m0 = blockIdx.x * 128;
    const int n0 = blockIdx.y * 128;

    {
        const float* xsg = g_xs + (size_t)m0 * NKB;
        for (int i = tid; i < 128 * NKB; i += 512) xs_s[i] = xsg[i];
        if (tid < NKB) ws_s[tid] = wsc[(n0 >> 7) * NKB + tid];
    }

    const uint32_t sa0 = su32(smem);

    // fragment source rows (validated mapping)
    const int a_row = wm * 32 + (lane & 7) + ((lane >> 3) & 1) * 8;
    const int a_k16 = ((lane >> 4) & 1) * 16;
    const int b_row = wn * 32 + (lane & 7) + ((lane >> 4) & 1) * 8;
    const int b_k16 = ((lane >> 3) & 1) * 16;

    // stage loader: 4 threads per row, 2 x 16B per matrix per thread;
    // global pointers precomputed once, stepped by kb*BLK
    const int l_row = tid >> 2;                    // 0..127
    const int l_c16 = (tid & 3) * 16;
    const uint8_t* agp = g_xq + (size_t)m0 * KDIM + (size_t)l_row * KDIM + l_c16;
    const uint8_t* bgp = g_wq + (size_t)n0 * KDIM + (size_t)l_row * KDIM + l_c16;
    int sw_st[2];
#pragma unroll
    for (int i = 0; i < 2; i++) {
        int off = l_row * 128 + l_c16 + i * 64;
        sw_st[i] = off ^ ((off >> 3) & 0x70);
    }

    float pacc[2][4][4];
#pragma unroll
    for (int i = 0; i < 2; i++)
#pragma unroll
        for (int j = 0; j < 4; j++)
#pragma unroll
            for (int c = 0; c < 4; c++) pacc[i][j][c] = 0.0f;

#define LOAD_STAGE(kb, s)                                                      \
    do {                                                                       \
        uint32_t da = sa0 + (s) * STG_BYTES;                                   \
        uint32_t db = da + 16384;                                              \
        _Pragma("unroll")                                                      \
        for (int i = 0; i < 2; i++) {                                          \
            CP16(da + sw_st[i], agp + (kb) * BLK + i * 64);                    \
            CP16(db + sw_st[i], bgp + (kb) * BLK + i * 64);                    \
        }                                                                      \
        asm volatile("cp.async.commit_group;");                                \
    } while (0)

// one k-block of compute + scale fixup, on stage s of the smem ring
#define COMPUTE_KB(kb, s)                                                      \
    do {                                                                       \
        const uint32_t ta = sa0 + (s) * STG_BYTES;                             \
        const uint32_t tb = ta + 16384;                                        \
        float lacc[2][4][4];                                                   \
        _Pragma("unroll")                                                      \
        for (int i = 0; i < 2; i++)                                            \
            _Pragma("unroll")                                                  \
            for (int j = 0; j < 4; j++)                                        \
                _Pragma("unroll")                                              \
                for (int c = 0; c < 4; c++) lacc[i][j][c] = 0.0f;              \
        _Pragma("unroll")                                                      \
        for (int kc = 0; kc < 4; kc++) {                                       \
            uint32_t af[2][4];                                                 \
            _Pragma("unroll")                                                  \
            for (int mf = 0; mf < 2; mf++) {                                   \
                int off = (a_row + mf * 16) * 128 + kc * 32 + a_k16;           \
                int sw  = off ^ ((off >> 3) & 0x70);                           \
                LDMX4(af[mf][0], af[mf][1], af[mf][2], af[mf][3], ta + sw);    \
            }                                                                  \
            uint32_t bf[4][2];                                                 \
            _Pragma("unroll")                                                  \
            for (int nj = 0; nj < 2; nj++) {                                   \
                int off = (b_row + nj * 16) * 128 + kc * 32 + b_k16;           \
                int sw  = off ^ ((off >> 3) & 0x70);                           \
                uint32_t r0, r1, r2, r3;                                       \
                LDMX4(r0, r1, r2, r3, tb + sw);                                \
                bf[nj * 2][0] = r0; bf[nj * 2][1] = r1;                        \
                bf[nj * 2 + 1][0] = r2; bf[nj * 2 + 1][1] = r3;                \
            }                                                                  \
            _Pragma("unroll")                                                  \
            for (int mf = 0; mf < 2; mf++)                                     \
                _Pragma("unroll")                                              \
                for (int nf = 0; nf < 4; nf++)                                 \
                    MMA_E4M3(lacc[mf][nf], af[mf], bf[nf]);                    \
        }                                                                      \
        const float wskb = ws_s[kb];                                           \
        _Pragma("unroll")                                                      \
        for (int mf = 0; mf < 2; mf++) {                                       \
            int r0 = wm * 32 + mf * 16 + (lane >> 2);                          \
            float s0 = xs_s[r0 * NKB + (kb)] * wskb;                           \
            float s1 = xs_s[(r0 + 8) * NKB + (kb)] * wskb;                     \
            _Pragma("unroll")                                                  \
            for (int nf = 0; nf < 4; nf++) {                                   \
                pacc[mf][nf][0] = fmaf(lacc[mf][nf][0], s0, pacc[mf][nf][0]);  \
                pacc[mf][nf][1] = fmaf(lacc[mf][nf][1], s0, pacc[mf][nf][1]);  \
                pacc[mf][nf][2] = fmaf(lacc[mf][nf][2], s1, pacc[mf][nf][2]);  \
                pacc[mf][nf][3] = fmaf(lacc[mf][nf][3], s1, pacc[mf][nf][3]);  \
            }                                                                  \
        }                                                                      \
    } while (0)

    LOAD_STAGE(0, 0);
    LOAD_STAGE(1, 1);

    // main loop (validated R6 structure): per-kb wait+barrier, 3-stage ring,
    // last iteration peeled for the final wait depth
    for (int kb = 0; kb < NKB - 1; kb++) {
        const int s = kb % 3;
        asm volatile("cp.async.wait_group 1;");
        __syncthreads();
        // stage (kb+2)%3 was last read in iteration kb-1 (completed before
        // this barrier), so it is free to refill now.
        if (kb + 2 < NKB) LOAD_STAGE(kb + 2, (kb + 2) % 3);
        COMPUTE_KB(kb, s);
    }
    {
        const int kb = NKB - 1, s = (NKB - 1) % 3;
        asm volatile("cp.async.wait_group 0;");
        __syncthreads();
        COMPUTE_KB(kb, s);
    }

    // epilogue: fragment-direct float2 stores
#pragma unroll
    for (int mf = 0; mf < 2; mf++) {
        int r0 = m0 + wm * 32 + mf * 16 + (lane >> 2);
#pragma unroll
        for (int nf = 0; nf < 4; nf++) {
            int c = n0 + wn * 32 + nf * 8 + (lane & 3) * 2;
            *reinterpret_cast<float2*>(out + (size_t)r0 * N + c) =
                make_float2(pacc[mf][nf][0], pacc[mf][nf][1]);
            *reinterpret_cast<float2*>(out + (size_t)(r0 + 8) * N + c) =
                make_float2(pacc[mf][nf][2], pacc[mf][nf][3]);
        }
    }
}

// ---------------------------------------------------------------------------
extern "C" void kernel_launch(void* const* d_in, const int* in_sizes, int n_in,
                              void* d_out, int out_size) {
    const float* x  = (const float*)d_in[0];
    const void*  w  = d_in[1];                     // fp8 weight, representation detected
    const float* ws = (const float*)d_in[2];       // [N/128, K/128] fp32
    float* out = (float*)d_out;

    const int M = in_sizes[0] / KDIM;              // 8192
    const int N = in_sizes[1] / KDIM;              // 2048
    const int WN = in_sizes[1];                    // N*K elements

    // fused prep: weight convert blocks + x quant blocks in one launch
    const int cb = WN / 4096;                      // 1024
    const int qb = (M * NKB) / 8;                  // 16384 (8 warps per block)
    prep_kernel<<<cb + qb, 256>>>(x, w, M, WN);

    static int smem_set = 0;
    if (!smem_set) {
        cudaFuncSetAttribute(gemm_fp8_mma,
                             cudaFuncAttributeMaxDynamicSharedMemorySize, SMEM_TOT);
        smem_set = 1;
    }
    dim3 grid(M / 128, N / 128);
    gemm_fp8_mma<<<grid, 512, SMEM_TOT>>>(ws, out, M, N);
}